// round 4
// baseline (speedup 1.0000x reference)
#include <cuda_runtime.h>
#include <cstdint>

// ---------------- problem constants ----------------
#define BATCH   64
#define MAXH    64
#define MAXW    32
#define DIM     512
#define SGRID   8
#define HID     64

// ---------------- tiling ----------------
// Persistent CTAs: grid 296 (2/SM). Each CTA owns one N-half (256 dims) and
// loops over 64-point tiles (1 batch, 2 i-rows x 32 j) with stride 148.
// 128 threads; thread tile = 16 points x 4 d-pairs (f32x2 accumulators).
#define TPB       128
#define NTILE     2048
#define GRIDMAIN  296

// SMEM layout (bytes):
//  [0,65536)      w2 half  [64 k][256 d] fp32
//  [65536,98304)  h buffer [64 p][64 k] float2 {h,h}  (aliased by ycan [2][8][128 f2] = 16KB)
//  [98304,99328)  b2 half  [256] fp32
//  [99328,99840)  tables: wy[2],y0[2],y1[2], wx[32],x0[32],x1[32]
#define OFF_W2    0
#define OFF_H     65536
#define OFF_B2    98304
#define OFF_TBL   99328
#define SMEM_BYTES 99840

typedef unsigned long long ull;

// precomputed h = gelu(u*w1[0,k] + v*w1[1,k] + b1[k]) : [131072 pts][64 k] fp32
__device__ __align__(16) float g_h[BATCH * MAXH * MAXW * HID];   // 33.5 MB

__device__ __forceinline__ float gelu_exact(float x) {
    // jax.nn.gelu(approximate=False): 0.5*x*(1+erf(x/sqrt(2)))
    return 0.5f * x * (1.0f + erff(x * 0.70710678118654752440f));
}

// ---------------- prep: h table ----------------
__global__ void hgq_prep(const float* __restrict__ w1, const float* __restrict__ b1,
                         const int* __restrict__ th, const int* __restrict__ tw)
{
    int idx = blockIdx.x * 256 + threadIdx.x;          // < 131072*64
    int p = idx >> 6, k = idx & 63;
    int bb = p >> 11, i = (p >> 5) & 63, j = p & 31;
    int H = min(max(th[bb], 1), MAXH);
    int W = min(max(tw[bb], 1), MAXW);
    float u = (H > 1) ? (float)i / (float)(H - 1) : 0.0f;
    float v = (W > 1) ? (float)j / (float)(W - 1) : 0.0f;
    g_h[idx] = gelu_exact(u * w1[k] + v * w1[HID + k] + b1[k]);
}

// ---------------- main persistent kernel ----------------
__global__ __launch_bounds__(TPB) void hgq_main(
    const float* __restrict__ canonical,   // [8,8,512]
    const float* __restrict__ w2,          // [64,512]
    const float* __restrict__ b2,          // [512]
    const int*   __restrict__ th,
    const int*   __restrict__ tw,
    float*       __restrict__ out)         // [64,64,32,512]
{
    extern __shared__ char smem[];
    float2*       shw2  = (float2*)(smem + OFF_W2);    // pair idx = k*128 + dp
    float2*       shh   = (float2*)(smem + OFF_H);     // {h,h}, idx = p*64 + k
    float2*       ycan  = (float2*)(smem + OFF_H);     // aliases h (post-GEMM)
    const float2* sb2   = (const float2*)(smem + OFF_B2);
    float*  t_wy = (float*)(smem + OFF_TBL);           // [2]
    int*    t_y0 = (int*)(smem + OFF_TBL + 8);         // [2]
    int*    t_y1 = (int*)(smem + OFF_TBL + 16);        // [2]
    float*  t_wx = (float*)(smem + OFF_TBL + 24);      // [32]
    int*    t_x0 = (int*)(smem + OFF_TBL + 152);       // [32]
    int*    t_x1 = (int*)(smem + OFF_TBL + 280);       // [32]

    const int tid  = threadIdx.x;
    const int wid  = tid >> 5;
    const int nx   = tid & 31;
    const int half = blockIdx.x & 1;
    const int t0   = blockIdx.x >> 1;

    // ---- one-time: stage w2 half and b2 half ----
    {
        const float* wsrc = w2 + half * 256;
        float4* ws = (float4*)(smem + OFF_W2);
        #pragma unroll
        for (int e = 0; e < 32; e++) {                 // 4096 float4
            int idx = tid + TPB * e;
            int k = idx >> 6, c4 = idx & 63;
            ws[idx] = __ldg((const float4*)(wsrc + k * DIM) + c4);
        }
        ((float2*)(smem + OFF_B2))[tid] = __ldg((const float2*)(b2 + half * 256) + tid);
    }

    for (int t = t0; t < NTILE; t += 148) {
        const int bb = t >> 5;
        const int i0 = (t & 31) << 1;
        const int H = min(max(__ldg(th + bb), 1), MAXH);
        const int W = min(max(__ldg(tw + bb), 1), MAXW);

        __syncthreads();   // previous epilogue done reading ycan / tables

        // per-tile tables
        if (tid < 32) {
            int j = tid;
            float v = (W > 1) ? (float)j / (float)(W - 1) : 0.0f;
            float sx = fminf(v * (float)(SGRID - 1), (float)(SGRID - 1));
            int x0 = (int)sx;
            t_wx[j] = sx - (float)x0;
            t_x0[j] = x0;
            t_x1[j] = min(x0 + 1, SGRID - 1);
        }
        if (tid >= 64 && tid < 66) {
            int r = tid - 64;
            int i = i0 + r;
            float u = (H > 1) ? (float)i / (float)(H - 1) : 0.0f;
            float sy = fminf(u * (float)(SGRID - 1), (float)(SGRID - 1));
            int y0 = (int)sy;
            t_wy[r] = sy - (float)y0;
            t_y0[r] = y0;
            t_y1[r] = min(y0 + 1, SGRID - 1);
        }

        // stage h tile (scalar global -> {h,h} dup in SMEM)
        {
            const float4* hg = (const float4*)(g_h + (size_t)t * (64 * HID));
            float4* hs4 = (float4*)(smem + OFF_H);
            #pragma unroll
            for (int e = 0; e < 8; e++) {              // 1024 float4 total
                int idx = tid + TPB * e;
                float4 v = __ldg(hg + idx);
                hs4[idx * 2]     = make_float4(v.x, v.x, v.y, v.y);
                hs4[idx * 2 + 1] = make_float4(v.z, v.z, v.w, v.w);
            }
        }
        __syncthreads();

        // ---- GEMM: acc[pp][c] += h[p][k] * w2[k][dp] ----
        ull acc[16][4];
        #pragma unroll
        for (int pp = 0; pp < 16; pp++)
            #pragma unroll
            for (int c = 0; c < 4; c++) acc[pp][c] = 0ull;

        const ull* shh_u = (const ull*)shh;
        const int pbase = wid * 16;

        #pragma unroll 4
        for (int k = 0; k < HID; k++) {
            ull wv[4];
            const ull* wk = (const ull*)shw2 + k * 128;
            #pragma unroll
            for (int c = 0; c < 4; c++) wv[c] = wk[nx + 32 * c];   // LDS.64 coalesced
            #pragma unroll
            for (int pp = 0; pp < 16; pp++) {
                ull h2 = shh_u[(pbase + pp) * HID + k];            // LDS.64 broadcast
                #pragma unroll
                for (int c = 0; c < 4; c++)
                    asm("fma.rn.f32x2 %0, %1, %2, %3;"
                        : "=l"(acc[pp][c]) : "l"(h2), "l"(wv[c]), "l"(acc[pp][c]));
            }
        }
        __syncthreads();   // h reads done; buffer becomes ycan

        // ---- build ycan[r][x][d2] = y-lerped canonical (fp32) ----
        {
            const float2* can2 = (const float2*)canonical + half * 128;
            #pragma unroll
            for (int e = 0; e < 16; e++) {             // 2048 float2 total
                int idx = tid + TPB * e;
                int d2 = idx & 127;
                int x  = (idx >> 7) & 7;
                int r  = idx >> 10;
                float wy = t_wy[r];
                float2 c0 = __ldg(can2 + ((size_t)(t_y0[r] * SGRID + x)) * 256 + d2);
                float2 c1 = __ldg(can2 + ((size_t)(t_y1[r] * SGRID + x)) * 256 + d2);
                ycan[idx] = make_float2(c0.x + wy * (c1.x - c0.x),
                                        c0.y + wy * (c1.y - c0.y));
            }
        }
        __syncthreads();

        // ---- epilogue: x-lerp + acc + b2 + mask, coalesced STG.64 ----
        {
            const int ir = wid >> 1;                   // i-row within tile
            const int i  = i0 + ir;
            const int jb = (wid & 1) * 16;
            float2 b2v[4];
            #pragma unroll
            for (int c = 0; c < 4; c++) b2v[c] = sb2[nx + 32 * c];

            #pragma unroll
            for (int pp = 0; pp < 16; pp++) {
                int j = jb + pp;
                bool msk = (i < H) && (j < W);
                int x0 = t_x0[j], x1 = t_x1[j];
                float wx = t_wx[j];
                const float2* y0p = ycan + (ir * 8 + x0) * 128;
                const float2* y1p = ycan + (ir * 8 + x1) * 128;
                float* op = out + ((size_t)((bb * 64 + i) * 32 + j)) * DIM + half * 256;

                #pragma unroll
                for (int c = 0; c < 4; c++) {
                    int dp = nx + 32 * c;
                    float2 a = y0p[dp];
                    float2 b = y1p[dp];
                    float bx = a.x + wx * (b.x - a.x);
                    float by = a.y + wx * (b.y - a.y);
                    ull A = acc[pp][c];
                    float ax = __uint_as_float((unsigned)A);
                    float ay = __uint_as_float((unsigned)(A >> 32));
                    float2 r;
                    r.x = msk ? (ax + bx + b2v[c].x) : 0.0f;
                    r.y = msk ? (ay + by + b2v[c].y) : 0.0f;
                    *(float2*)(op + dp * 2) = r;
                }
            }
        }
    }
}

// ---------------- mask tail ----------------
__global__ void hgq_mask(const int* __restrict__ th, const int* __restrict__ tw,
                         float* __restrict__ outt, int tail)
{
    int idx = blockIdx.x * 256 + threadIdx.x;
    if (idx >= tail) return;
    float val = 0.0f;
    if (idx < BATCH * MAXH * MAXW) {
        int bb = idx >> 11;
        int r  = idx & 2047;
        int i  = r >> 5;
        int j  = r & 31;
        int H = min(max(th[bb], 1), MAXH);
        int W = min(max(tw[bb], 1), MAXW);
        val = (i < H && j < W) ? 1.0f : 0.0f;
    }
    outt[idx] = val;
}

extern "C" void kernel_launch(void* const* d_in, const int* in_sizes, int n_in,
                              void* d_out, int out_size)
{
    const float* canonical = (const float*)d_in[0];
    const float* w1        = (const float*)d_in[1];
    const float* b1        = (const float*)d_in[2];
    const float* w2        = (const float*)d_in[3];
    const float* b2        = (const float*)d_in[4];
    const int*   th        = (const int*)d_in[6];
    const int*   tw        = (const int*)d_in[7];
    float* out = (float*)d_out;

    hgq_prep<<<(BATCH * MAXH * MAXW * HID) / 256, 256>>>(w1, b1, th, tw);

    cudaFuncSetAttribute(hgq_main, cudaFuncAttributeMaxDynamicSharedMemorySize, SMEM_BYTES);
    hgq_main<<<GRIDMAIN, TPB, SMEM_BYTES>>>(canonical, w2, b2, th, tw, out);

    const int qelems = BATCH * MAXH * MAXW * DIM;   // 67108864
    int tail = out_size - qelems;
    if (tail > 0) {
        hgq_mask<<<(tail + 255) / 256, 256>>>(th, tw, out + qelems, tail);
    }
}

// round 6
// speedup vs baseline: 2.1318x; 2.1318x over previous
#include <cuda_runtime.h>
#include <cstdint>

// ---------------- problem constants ----------------
#define BATCH   64
#define MAXH    64
#define MAXW    32
#define DIM     512
#define SGRID   8
#define HID     64

#define TPB       128
#define GRIDMAIN  296      // 2 CTAs per SM

// SMEM layout (bytes)
//  [0,65536)        w2 half [64 k][256 d] fp32
//  [65536,98304)    h buffer [64 p][64 k] float2 {h,h}
//  [98304,99328)    b2 half [256] fp32
//  [99328,99840)    w1 cache: w1u[64], w1v[64]
//  [99840,100096)   b1[64]
//  [100096,101632)  per-point meta: m_u[64], m_v[64], m_wy[64], m_wx[64],
//                   m_geom[64], m_addr[64]
//  [101632,101892)  s_base[65]
//  [101892,102148)  s_hw[64]
#define OFF_W2    0
#define OFF_H     65536
#define OFF_B2    98304
#define OFF_W1    99328
#define OFF_B1    99840
#define OFF_MU    100096
#define OFF_MV    100352
#define OFF_MWY   100608
#define OFF_MWX   100864
#define OFF_GEOM  101120
#define OFF_ADDR  101376
#define OFF_BASE  101632
#define OFF_HW    101892
#define SMEM_BYTES 102400

typedef unsigned long long ull;

__device__ int g_base[BATCH + 1];   // prefix sums of H*W
__device__ int g_hw[BATCH];         // (H<<16)|W clipped

__device__ __forceinline__ float gelu_exact(float x) {
    return 0.5f * x * (1.0f + erff(x * 0.70710678118654752440f));
}

// ---------------- scan: per-batch active counts + prefix ----------------
__global__ void hgq_scan(const int* __restrict__ th, const int* __restrict__ tw)
{
    if (threadIdx.x == 0) {
        int run = 0;
        for (int b = 0; b < BATCH; b++) {
            int H = min(max(th[b], 1), MAXH);
            int W = min(max(tw[b], 1), MAXW);
            g_base[b] = run;
            g_hw[b] = (H << 16) | W;
            run += H * W;
        }
        g_base[BATCH] = run;
    }
}

// ---------------- zero-fill masked region ----------------
__global__ __launch_bounds__(256) void hgq_zero(
    const int* __restrict__ th, const int* __restrict__ tw,
    float* __restrict__ out)
{
    const int blk = blockIdx.x;        // 0..4095 = (b,i)
    const int b = blk >> 6, i = blk & 63;
    const int H = min(max(__ldg(th + b), 1), MAXH);
    const int W = min(max(__ldg(tw + b), 1), MAXW);
    float4* row = (float4*)(out + ((size_t)blk) * (MAXW * DIM));
    const float4 z = make_float4(0.f, 0.f, 0.f, 0.f);
    if (i >= H) {
        #pragma unroll
        for (int e = 0; e < (MAXW * DIM / 4) / 256; e++)   // 16 iters
            row[threadIdx.x + 256 * e] = z;
    } else if (W < MAXW) {
        int start4 = W * (DIM / 4);                        // float4 index
        int cnt4 = (MAXW - W) * (DIM / 4);
        for (int e = threadIdx.x; e < cnt4; e += 256)
            row[start4 + e] = z;
    }
}

// ---------------- main persistent compacted-GEMM kernel ----------------
__global__ __launch_bounds__(TPB) void hgq_main(
    const float* __restrict__ canonical,   // [8,8,512]
    const float* __restrict__ w1,          // [2,64]
    const float* __restrict__ b1,          // [64]
    const float* __restrict__ w2,          // [64,512]
    const float* __restrict__ b2,          // [512]
    float*       __restrict__ out)         // [64,64,32,512]
{
    extern __shared__ char smem[];
    float2* shh   = (float2*)(smem + OFF_H);
    const float2* sb2 = (const float2*)(smem + OFF_B2);
    float* s_w1u  = (float*)(smem + OFF_W1);
    float* s_w1v  = (float*)(smem + OFF_W1 + 256);
    float* s_b1   = (float*)(smem + OFF_B1);
    float* m_u    = (float*)(smem + OFF_MU);
    float* m_v    = (float*)(smem + OFF_MV);
    float* m_wy   = (float*)(smem + OFF_MWY);
    float* m_wx   = (float*)(smem + OFF_MWX);
    int*   m_geom = (int*)(smem + OFF_GEOM);
    int*   m_addr = (int*)(smem + OFF_ADDR);
    int*   s_base = (int*)(smem + OFF_BASE);   // [65]
    int*   s_hw   = (int*)(smem + OFF_HW);     // [64]

    const int tid  = threadIdx.x;
    const int wid  = tid >> 5;
    const int nx   = tid & 31;
    const int half = blockIdx.x & 1;
    const int t0   = blockIdx.x >> 1;

    // ---- one-time staging ----
    {
        const float* wsrc = w2 + half * 256;
        float4* ws = (float4*)(smem + OFF_W2);
        #pragma unroll
        for (int e = 0; e < 32; e++) {
            int idx = tid + TPB * e;
            int k = idx >> 6, c4 = idx & 63;
            ws[idx] = __ldg((const float4*)(wsrc + k * DIM) + c4);
        }
        ((float2*)(smem + OFF_B2))[tid] = __ldg((const float2*)(b2 + half * 256) + tid);
        if (tid < 64) {
            s_w1u[tid] = __ldg(w1 + tid);
            s_w1v[tid] = __ldg(w1 + HID + tid);
            s_b1[tid]  = __ldg(b1 + tid);
            s_hw[tid]  = g_hw[tid];
        }
        if (tid < 65) s_base[tid] = g_base[tid];
    }
    __syncthreads();
    const int total = s_base[BATCH];

    for (int t = t0; t * 64 < total; t += 148) {
        const int q0 = t * 64;

        __syncthreads();   // prior epilogue done reading meta

        // ---- phase 1: per-point meta (threads 0..63) ----
        if (tid < 64) {
            int q = q0 + tid;
            if (q < total) {
                // binary search batch
                int lo = 0, hi = BATCH;
                while (hi - lo > 1) {
                    int mid = (lo + hi) >> 1;
                    if (q >= s_base[mid]) lo = mid; else hi = mid;
                }
                int b = lo;
                int hw = s_hw[b];
                int H = hw >> 16, W = hw & 0xFFFF;
                int r = q - s_base[b];
                int i = r / W;
                int j = r - i * W;
                float u = (H > 1) ? (float)i / (float)(H - 1) : 0.0f;
                float v = (W > 1) ? (float)j / (float)(W - 1) : 0.0f;
                float sy = fminf(u * (float)(SGRID - 1), (float)(SGRID - 1));
                float sx = fminf(v * (float)(SGRID - 1), (float)(SGRID - 1));
                int y0 = (int)sy, x0 = (int)sx;
                int y1 = min(y0 + 1, SGRID - 1);
                int x1 = min(x0 + 1, SGRID - 1);
                m_u[tid] = u;  m_v[tid] = v;
                m_wy[tid] = sy - (float)y0;
                m_wx[tid] = sx - (float)x0;
                m_geom[tid] = y0 | (y1 << 8) | (x0 << 16) | (x1 << 24);
                m_addr[tid] = (b << 11) | (i << 5) | j;
            } else {
                m_u[tid] = 0.f; m_v[tid] = 0.f;
                m_wy[tid] = 0.f; m_wx[tid] = 0.f;
                m_geom[tid] = 0;
                m_addr[tid] = -1;
            }
        }
        __syncthreads();

        // ---- phase 2: h = gelu(u*w1u + v*w1v + b1), dup {h,h} ----
        {
            int p = tid >> 1;
            int kb = (tid & 1) * 32;
            float u = m_u[p], v = m_v[p];
            float2* dst = shh + p * HID + kb;
            #pragma unroll
            for (int c = 0; c < 32; c++) {
                int k = kb + c;
                float g = gelu_exact(u * s_w1u[k] + v * s_w1v[k] + s_b1[k]);
                dst[c] = make_float2(g, g);
            }
        }
        __syncthreads();

        // ---- GEMM: acc[pp][c] += h[p][k] * w2[k][dp] ----
        ull acc[16][4];
        #pragma unroll
        for (int pp = 0; pp < 16; pp++)
            #pragma unroll
            for (int c = 0; c < 4; c++) acc[pp][c] = 0ull;

        const ull* shh_u = (const ull*)shh;
        const ull* shw2_u = (const ull*)(smem + OFF_W2);
        const int pbase = wid * 16;

        #pragma unroll 4
        for (int k = 0; k < HID; k++) {
            ull wv[4];
            const ull* wk = shw2_u + k * 128;
            #pragma unroll
            for (int c = 0; c < 4; c++) wv[c] = wk[nx + 32 * c];
            #pragma unroll
            for (int pp = 0; pp < 16; pp++) {
                ull h2 = shh_u[(pbase + pp) * HID + k];
                #pragma unroll
                for (int c = 0; c < 4; c++)
                    asm("fma.rn.f32x2 %0, %1, %2, %3;"
                        : "=l"(acc[pp][c]) : "l"(h2), "l"(wv[c]), "l"(acc[pp][c]));
            }
        }

        // ---- epilogue: bilinear gathers + acc + b2, coalesced STG.64 ----
        {
            const float2* can2 = (const float2*)canonical + half * 128;
            float2 b2v[4];
            #pragma unroll
            for (int c = 0; c < 4; c++) b2v[c] = sb2[nx + 32 * c];

            #pragma unroll
            for (int pp = 0; pp < 16; pp++) {
                int p = pbase + pp;
                int ad = m_addr[p];
                if (ad < 0) continue;
                int geom = m_geom[p];
                int y0 = geom & 0xFF, y1 = (geom >> 8) & 0xFF;
                int x0 = (geom >> 16) & 0xFF, x1 = (geom >> 24) & 0xFF;
                float wy = m_wy[p], wx = m_wx[p];
                const float2* p00 = can2 + (size_t)(y0 * SGRID + x0) * 256;
                const float2* p01 = can2 + (size_t)(y0 * SGRID + x1) * 256;
                const float2* p10 = can2 + (size_t)(y1 * SGRID + x0) * 256;
                const float2* p11 = can2 + (size_t)(y1 * SGRID + x1) * 256;
                float w00 = (1.f - wy) * (1.f - wx), w01 = (1.f - wy) * wx;
                float w10 = wy * (1.f - wx),         w11 = wy * wx;
                float* op = out + ((size_t)ad) * DIM + half * 256;

                #pragma unroll
                for (int c = 0; c < 4; c++) {
                    int dp = nx + 32 * c;
                    float2 q00 = __ldg(p00 + dp);
                    float2 q01 = __ldg(p01 + dp);
                    float2 q10 = __ldg(p10 + dp);
                    float2 q11 = __ldg(p11 + dp);
                    float bx = w00 * q00.x + w01 * q01.x + w10 * q10.x + w11 * q11.x;
                    float by = w00 * q00.y + w01 * q01.y + w10 * q10.y + w11 * q11.y;
                    ull A = acc[pp][c];
                    float2 r;
                    r.x = __uint_as_float((unsigned)A) + bx + b2v[c].x;
                    r.y = __uint_as_float((unsigned)(A >> 32)) + by + b2v[c].y;
                    *(float2*)(op + dp * 2) = r;
                }
            }
        }
    }
}

// ---------------- mask tail ----------------
__global__ void hgq_mask(const int* __restrict__ th, const int* __restrict__ tw,
                         float* __restrict__ outt, int tail)
{
    int idx = blockIdx.x * 256 + threadIdx.x;
    if (idx >= tail) return;
    float val = 0.0f;
    if (idx < BATCH * MAXH * MAXW) {
        int bb = idx >> 11;
        int r  = idx & 2047;
        int i  = r >> 5;
        int j  = r & 31;
        int H = min(max(th[bb], 1), MAXH);
        int W = min(max(tw[bb], 1), MAXW);
        val = (i < H && j < W) ? 1.0f : 0.0f;
    }
    outt[idx] = val;
}

extern "C" void kernel_launch(void* const* d_in, const int* in_sizes, int n_in,
                              void* d_out, int out_size)
{
    const float* canonical = (const float*)d_in[0];
    const float* w1        = (const float*)d_in[1];
    const float* b1        = (const float*)d_in[2];
    const float* w2        = (const float*)d_in[3];
    const float* b2        = (const float*)d_in[4];
    const int*   th        = (const int*)d_in[6];
    const int*   tw        = (const int*)d_in[7];
    float* out = (float*)d_out;

    hgq_scan<<<1, 32>>>(th, tw);
    hgq_zero<<<BATCH * MAXH, 256>>>(th, tw, out);

    cudaFuncSetAttribute(hgq_main, cudaFuncAttributeMaxDynamicSharedMemorySize, SMEM_BYTES);
    hgq_main<<<GRIDMAIN, TPB, SMEM_BYTES>>>(canonical, w1, b1, w2, b2, out);

    const int qelems = BATCH * MAXH * MAXW * DIM;
    int tail = out_size - qelems;
    if (tail > 0) {
        hgq_mask<<<(tail + 255) / 256, 256>>>(th, tw, out + qelems, tail);
    }
}

// round 7
// speedup vs baseline: 2.2538x; 1.0572x over previous
#include <cuda_runtime.h>
#include <cstdint>

// ---------------- problem constants ----------------
#define BATCH   64
#define MAXH    64
#define MAXW    32
#define DIM     512
#define SGRID   8
#define HID     64

#define TPB       128
#define GRIDMAIN  296      // 2 CTAs per SM
#define QELEMS    (BATCH * MAXH * MAXW * DIM)
#define NROWS     (BATCH * MAXH)          // 4096 (b,i) row units

// SMEM layout (bytes)
#define OFF_W2    0        // w2 half [64 k][256 d] fp32                (65536)
#define OFF_H     65536    // h buffer [64 p][64 k] float2 {h,h}        (32768)
#define OFF_B2    98304    // b2 half [256] fp32                        (1024)
#define OFF_W1    99328    // w1u[64], w1v[64]                          (512)
#define OFF_B1    99840    // b1[64]                                    (256)
#define OFF_MU    100096
#define OFF_MV    100352
#define OFF_MWY   100608
#define OFF_MWX   100864
#define OFF_GEOM  101120
#define OFF_ADDR  101376
#define OFF_BASE  101632   // s_base[65]                                (260)
#define OFF_HW    101892   // s_hw[64]                                  (256)
#define SMEM_BYTES 102400

typedef unsigned long long ull;

__device__ __forceinline__ float gelu_exact(float x) {
    return 0.5f * x * (1.0f + erff(x * 0.70710678118654752440f));
}

// zero/mask one (b,i) row unit: zero masked query region, write mask floats.
__device__ __forceinline__ void do_row(
    int r, const int* s_hw, float* __restrict__ out,
    float* __restrict__ mout, int tail, int tid)
{
    const int b = r >> 6, i = r & 63;
    const int hw = s_hw[b];
    const int H = hw >> 16, W = hw & 0xFFFF;
    float4* row = (float4*)(out + ((size_t)r) * (MAXW * DIM));
    const float4 z = make_float4(0.f, 0.f, 0.f, 0.f);
    if (i >= H) {
        #pragma unroll
        for (int e = 0; e < (MAXW * DIM / 4) / TPB; e++)   // 32 iters
            row[tid + TPB * e] = z;
    } else if (W < MAXW) {
        int start4 = W * (DIM / 4);
        int cnt4 = (MAXW - W) * (DIM / 4);
        for (int e = tid; e < cnt4; e += TPB)
            row[start4 + e] = z;
    }
    if (tail > 0 && tid < 32) {
        int idx = r * 32 + tid;
        if (idx < tail)
            mout[idx] = (i < H && tid < W) ? 1.0f : 0.0f;
    }
}

// ---------------- single fused persistent kernel ----------------
__global__ __launch_bounds__(TPB) void hgq_all(
    const float* __restrict__ canonical,   // [8,8,512]
    const float* __restrict__ w1,          // [2,64]
    const float* __restrict__ b1,          // [64]
    const float* __restrict__ w2,          // [64,512]
    const float* __restrict__ b2,          // [512]
    const int*   __restrict__ th,
    const int*   __restrict__ tw,
    float*       __restrict__ out,         // [64,64,32,512] (+ mask tail)
    int          out_size)
{
    extern __shared__ char smem[];
    float2* shh   = (float2*)(smem + OFF_H);
    const float2* sb2 = (const float2*)(smem + OFF_B2);
    float* s_w1u  = (float*)(smem + OFF_W1);
    float* s_w1v  = (float*)(smem + OFF_W1 + 256);
    float* s_b1   = (float*)(smem + OFF_B1);
    float* m_u    = (float*)(smem + OFF_MU);
    float* m_v    = (float*)(smem + OFF_MV);
    float* m_wy   = (float*)(smem + OFF_MWY);
    float* m_wx   = (float*)(smem + OFF_MWX);
    int*   m_geom = (int*)(smem + OFF_GEOM);
    int*   m_addr = (int*)(smem + OFF_ADDR);
    int*   s_base = (int*)(smem + OFF_BASE);   // [65]
    int*   s_hw   = (int*)(smem + OFF_HW);     // [64]

    const int tid  = threadIdx.x;
    const int wid  = tid >> 5;
    const int nx   = tid & 31;
    const int half = blockIdx.x & 1;
    const int t0   = blockIdx.x >> 1;
    const int tail = out_size - QELEMS;
    float* mout = out + QELEMS;

    // ---- one-time staging ----
    {
        const float* wsrc = w2 + half * 256;
        float4* ws = (float4*)(smem + OFF_W2);
        #pragma unroll
        for (int e = 0; e < 32; e++) {
            int idx = tid + TPB * e;
            int k = idx >> 6, c4 = idx & 63;
            ws[idx] = __ldg((const float4*)(wsrc + k * DIM) + c4);
        }
        ((float2*)(smem + OFF_B2))[tid] = __ldg((const float2*)(b2 + half * 256) + tid);
        if (tid < 64) {
            s_w1u[tid] = __ldg(w1 + tid);
            s_w1v[tid] = __ldg(w1 + HID + tid);
            s_b1[tid]  = __ldg(b1 + tid);
            int H = min(max(__ldg(th + tid), 1), MAXH);
            int W = min(max(__ldg(tw + tid), 1), MAXW);
            s_hw[tid] = (H << 16) | W;
        }
    }
    __syncthreads();

    // ---- in-CTA prefix scan over 64 batch sizes (warp 0) ----
    if (wid == 0) {
        int hw0 = s_hw[2 * nx], hw1 = s_hw[2 * nx + 1];
        int c0 = (hw0 >> 16) * (hw0 & 0xFFFF);
        int c1 = (hw1 >> 16) * (hw1 & 0xFFFF);
        int pair = c0 + c1;
        int incl = pair;
        #pragma unroll
        for (int d = 1; d < 32; d <<= 1) {
            int n = __shfl_up_sync(0xFFFFFFFF, incl, d);
            if (nx >= d) incl += n;
        }
        int excl = incl - pair;
        s_base[2 * nx]     = excl;
        s_base[2 * nx + 1] = excl + c0;
        if (nx == 31) s_base[64] = incl;
    }
    __syncthreads();
    const int total = s_base[BATCH];

    int zr = blockIdx.x;       // zero/mask row cursor (uniform across CTA)

    for (int t = t0; t * 64 < total; t += 148) {
        const int q0 = t * 64;

        __syncthreads();   // prior epilogue done reading meta

        // ---- phase 1: per-point meta (threads 0..63) ----
        if (tid < 64) {
            int q = q0 + tid;
            if (q < total) {
                int lo = 0, hi = BATCH;
                while (hi - lo > 1) {
                    int mid = (lo + hi) >> 1;
                    if (q >= s_base[mid]) lo = mid; else hi = mid;
                }
                int b = lo;
                int hw = s_hw[b];
                int H = hw >> 16, W = hw & 0xFFFF;
                int r = q - s_base[b];
                int i = r / W;
                int j = r - i * W;
                float u = (H > 1) ? (float)i / (float)(H - 1) : 0.0f;
                float v = (W > 1) ? (float)j / (float)(W - 1) : 0.0f;
                float sy = fminf(u * (float)(SGRID - 1), (float)(SGRID - 1));
                float sx = fminf(v * (float)(SGRID - 1), (float)(SGRID - 1));
                int y0 = (int)sy, x0 = (int)sx;
                int y1 = min(y0 + 1, SGRID - 1);
                int x1 = min(x0 + 1, SGRID - 1);
                m_u[tid] = u;  m_v[tid] = v;
                m_wy[tid] = sy - (float)y0;
                m_wx[tid] = sx - (float)x0;
                m_geom[tid] = y0 | (y1 << 8) | (x0 << 16) | (x1 << 24);
                m_addr[tid] = (b << 11) | (i << 5) | j;
            } else {
                m_u[tid] = 0.f; m_v[tid] = 0.f;
                m_wy[tid] = 0.f; m_wx[tid] = 0.f;
                m_geom[tid] = 0;
                m_addr[tid] = -1;
            }
        }
        __syncthreads();

        // ---- phase 2: h = gelu(u*w1u + v*w1v + b1), dup {h,h} ----
        {
            int p = tid >> 1;
            int kb = (tid & 1) * 32;
            float u = m_u[p], v = m_v[p];
            float2* dst = shh + p * HID + kb;
            #pragma unroll
            for (int c = 0; c < 32; c++) {
                int k = kb + c;
                float g = gelu_exact(u * s_w1u[k] + v * s_w1v[k] + s_b1[k]);
                dst[c] = make_float2(g, g);
            }
        }
        __syncthreads();

        // ---- GEMM: acc[pp][c] += h[p][k] * w2[k][dp] ----
        ull acc[16][4];
        #pragma unroll
        for (int pp = 0; pp < 16; pp++)
            #pragma unroll
            for (int c = 0; c < 4; c++) acc[pp][c] = 0ull;

        const ull* shh_u = (const ull*)shh;
        const ull* shw2_u = (const ull*)(smem + OFF_W2);
        const int pbase = wid * 16;

        #pragma unroll 4
        for (int k = 0; k < HID; k++) {
            ull wv[4];
            const ull* wk = shw2_u + k * 128;
            #pragma unroll
            for (int c = 0; c < 4; c++) wv[c] = wk[nx + 32 * c];
            #pragma unroll
            for (int pp = 0; pp < 16; pp++) {
                ull h2 = shh_u[(pbase + pp) * HID + k];
                #pragma unroll
                for (int c = 0; c < 4; c++)
                    asm("fma.rn.f32x2 %0, %1, %2, %3;"
                        : "=l"(acc[pp][c]) : "l"(h2), "l"(wv[c]), "l"(acc[pp][c]));
            }
        }

        // ---- epilogue: bilinear gathers + acc + b2, coalesced STG.64 ----
        {
            const float2* can2 = (const float2*)canonical + half * 128;
            float2 b2v[4];
            #pragma unroll
            for (int c = 0; c < 4; c++) b2v[c] = sb2[nx + 32 * c];

            #pragma unroll
            for (int pp = 0; pp < 16; pp++) {
                int p = pbase + pp;
                int ad = m_addr[p];
                if (ad < 0) continue;
                int geom = m_geom[p];
                int y0 = geom & 0xFF, y1 = (geom >> 8) & 0xFF;
                int x0 = (geom >> 16) & 0xFF, x1 = (geom >> 24) & 0xFF;
                float wy = m_wy[p], wx = m_wx[p];
                const float2* p00 = can2 + (size_t)(y0 * SGRID + x0) * 256;
                const float2* p01 = can2 + (size_t)(y0 * SGRID + x1) * 256;
                const float2* p10 = can2 + (size_t)(y1 * SGRID + x0) * 256;
                const float2* p11 = can2 + (size_t)(y1 * SGRID + x1) * 256;
                float w00 = (1.f - wy) * (1.f - wx), w01 = (1.f - wy) * wx;
                float w10 = wy * (1.f - wx),         w11 = wy * wx;
                float* op = out + ((size_t)ad) * DIM + half * 256;

                #pragma unroll
                for (int c = 0; c < 4; c++) {
                    int dp = nx + 32 * c;
                    float2 q00 = __ldg(p00 + dp);
                    float2 q01 = __ldg(p01 + dp);
                    float2 q10 = __ldg(p10 + dp);
                    float2 q11 = __ldg(p11 + dp);
                    float bx = w00 * q00.x + w01 * q01.x + w10 * q10.x + w11 * q11.x;
                    float by = w00 * q00.y + w01 * q01.y + w10 * q10.y + w11 * q11.y;
                    ull A = acc[pp][c];
                    float2 r;
                    r.x = __uint_as_float((unsigned)A) + bx + b2v[c].x;
                    r.y = __uint_as_float((unsigned)(A >> 32)) + by + b2v[c].y;
                    *(float2*)(op + dp * 2) = r;
                }
            }
        }

        // ---- interleaved zero/mask rows (overlap DRAM under next tile's FMA) ----
        #pragma unroll 1
        for (int z = 0; z < 4 && zr < NROWS; z++, zr += GRIDMAIN)
            do_row(zr, s_hw, out, mout, tail, tid);
    }

    // ---- remaining zero/mask rows ----
    #pragma unroll 1
    while (zr < NROWS) { do_row(zr, s_hw, out, mout, tail, tid); zr += GRIDMAIN; }

    // ---- any padding past qelems + 131072 (CTA 0) ----
    if (blockIdx.x == 0 && tail > NROWS * 32) {
        for (int e = NROWS * 32 + tid; e < tail; e += TPB)
            mout[e] = 0.0f;
    }
}

extern "C" void kernel_launch(void* const* d_in, const int* in_sizes, int n_in,
                              void* d_out, int out_size)
{
    const float* canonical = (const float*)d_in[0];
    const float* w1        = (const float*)d_in[1];
    const float* b1        = (const float*)d_in[2];
    const float* w2        = (const float*)d_in[3];
    const float* b2        = (const float*)d_in[4];
    const int*   th        = (const int*)d_in[6];
    const int*   tw        = (const int*)d_in[7];
    float* out = (float*)d_out;

    cudaFuncSetAttribute(hgq_all, cudaFuncAttributeMaxDynamicSharedMemorySize, SMEM_BYTES);
    hgq_all<<<GRIDMAIN, TPB, SMEM_BYTES>>>(canonical, w1, b1, w2, b2, th, tw,
                                           out, out_size);
}

// round 8
// speedup vs baseline: 2.3005x; 1.0208x over previous
#include <cuda_runtime.h>
#include <cstdint>

// ---------------- problem constants ----------------
#define BATCH   64
#define MAXH    64
#define MAXW    32
#define DIM     512
#define SGRID   8
#define HID     64

#define TPB       256
#define GRIDMAIN  296      // 2 CTAs per SM
#define QELEMS    (BATCH * MAXH * MAXW * DIM)
#define NROWS     (BATCH * MAXH)          // 4096 (b,i) row units

// SMEM layout (bytes)
#define OFF_W2    0        // w2 half [64 k][256 d] fp32                (65536)
#define OFF_H     65536    // h buffer [64 p][64 k] float2 {h,h}        (32768)
#define OFF_B2    98304    // b2 half [256] fp32                        (1024)
#define OFF_W1    99328    // w1u[64], w1v[64]                          (512)
#define OFF_B1    99840    // b1[64]                                    (256)
#define OFF_MU    100096
#define OFF_MV    100352
#define OFF_MWY   100608
#define OFF_MWX   100864
#define OFF_GEOM  101120
#define OFF_ADDR  101376
#define OFF_BASE  101632   // s_base[65]                                (260)
#define OFF_HW    101892   // s_hw[64]                                  (256)
#define SMEM_BYTES 102400

typedef unsigned long long ull;

__device__ __forceinline__ float gelu_exact(float x) {
    return 0.5f * x * (1.0f + erff(x * 0.70710678118654752440f));
}

// zero/mask one (b,i) row unit: zero masked query region, write mask floats.
__device__ __forceinline__ void do_row(
    int r, const int* s_hw, float* __restrict__ out,
    float* __restrict__ mout, int tail, int tid)
{
    const int b = r >> 6, i = r & 63;
    const int hw = s_hw[b];
    const int H = hw >> 16, W = hw & 0xFFFF;
    float4* row = (float4*)(out + ((size_t)r) * (MAXW * DIM));
    const float4 z = make_float4(0.f, 0.f, 0.f, 0.f);
    if (i >= H) {
        #pragma unroll
        for (int e = 0; e < (MAXW * DIM / 4) / TPB; e++)   // 16 iters
            row[tid + TPB * e] = z;
    } else if (W < MAXW) {
        int start4 = W * (DIM / 4);
        int cnt4 = (MAXW - W) * (DIM / 4);
        for (int e = tid; e < cnt4; e += TPB)
            row[start4 + e] = z;
    }
    if (tail > 0 && tid < 32) {
        int idx = r * 32 + tid;
        if (idx < tail)
            mout[idx] = (i < H && tid < W) ? 1.0f : 0.0f;
    }
}

// ---------------- single fused persistent kernel ----------------
__global__ __launch_bounds__(TPB, 2) void hgq_all(
    const float* __restrict__ canonical,   // [8,8,512]
    const float* __restrict__ w1,          // [2,64]
    const float* __restrict__ b1,          // [64]
    const float* __restrict__ w2,          // [64,512]
    const float* __restrict__ b2,          // [512]
    const int*   __restrict__ th,
    const int*   __restrict__ tw,
    float*       __restrict__ out,         // [64,64,32,512] (+ mask tail)
    int          out_size)
{
    extern __shared__ char smem[];
    float2* shh   = (float2*)(smem + OFF_H);
    const float2* sb2 = (const float2*)(smem + OFF_B2);
    float* s_w1u  = (float*)(smem + OFF_W1);
    float* s_w1v  = (float*)(smem + OFF_W1 + 256);
    float* s_b1   = (float*)(smem + OFF_B1);
    float* m_u    = (float*)(smem + OFF_MU);
    float* m_v    = (float*)(smem + OFF_MV);
    float* m_wy   = (float*)(smem + OFF_MWY);
    float* m_wx   = (float*)(smem + OFF_MWX);
    int*   m_geom = (int*)(smem + OFF_GEOM);
    int*   m_addr = (int*)(smem + OFF_ADDR);
    int*   s_base = (int*)(smem + OFF_BASE);   // [65]
    int*   s_hw   = (int*)(smem + OFF_HW);     // [64]

    const int tid  = threadIdx.x;
    const int wid  = tid >> 5;
    const int nx   = tid & 31;
    const int half = blockIdx.x & 1;
    const int t0   = blockIdx.x >> 1;
    const int tail = out_size - QELEMS;
    float* mout = out + QELEMS;

    // ---- one-time staging ----
    {
        const float* wsrc = w2 + half * 256;
        float4* ws = (float4*)(smem + OFF_W2);
        #pragma unroll
        for (int e = 0; e < 16; e++) {                 // 4096 float4
            int idx = tid + TPB * e;
            int k = idx >> 6, c4 = idx & 63;
            ws[idx] = __ldg((const float4*)(wsrc + k * DIM) + c4);
        }
        if (tid < 128)
            ((float2*)(smem + OFF_B2))[tid] = __ldg((const float2*)(b2 + half * 256) + tid);
        if (tid < 64) {
            s_w1u[tid] = __ldg(w1 + tid);
            s_w1v[tid] = __ldg(w1 + HID + tid);
            s_b1[tid]  = __ldg(b1 + tid);
            int H = min(max(__ldg(th + tid), 1), MAXH);
            int W = min(max(__ldg(tw + tid), 1), MAXW);
            s_hw[tid] = (H << 16) | W;
        }
    }
    __syncthreads();

    // ---- in-CTA prefix scan over 64 batch sizes (warp 0) ----
    if (wid == 0) {
        int hw0 = s_hw[2 * nx], hw1 = s_hw[2 * nx + 1];
        int c0 = (hw0 >> 16) * (hw0 & 0xFFFF);
        int c1 = (hw1 >> 16) * (hw1 & 0xFFFF);
        int pair = c0 + c1;
        int incl = pair;
        #pragma unroll
        for (int d = 1; d < 32; d <<= 1) {
            int n = __shfl_up_sync(0xFFFFFFFF, incl, d);
            if (nx >= d) incl += n;
        }
        int excl = incl - pair;
        s_base[2 * nx]     = excl;
        s_base[2 * nx + 1] = excl + c0;
        if (nx == 31) s_base[64] = incl;
    }
    __syncthreads();
    const int total = s_base[BATCH];

    int zr = blockIdx.x;       // zero/mask row cursor (uniform across CTA)

    for (int t = t0; t * 64 < total; t += 148) {
        const int q0 = t * 64;

        __syncthreads();   // prior epilogue done reading meta

        // ---- phase 1: per-point meta (threads 0..63) ----
        if (tid < 64) {
            int q = q0 + tid;
            if (q < total) {
                int lo = 0, hi = BATCH;
                while (hi - lo > 1) {
                    int mid = (lo + hi) >> 1;
                    if (q >= s_base[mid]) lo = mid; else hi = mid;
                }
                int b = lo;
                int hw = s_hw[b];
                int H = hw >> 16, W = hw & 0xFFFF;
                int r = q - s_base[b];
                int i = r / W;
                int j = r - i * W;
                float u = (H > 1) ? (float)i / (float)(H - 1) : 0.0f;
                float v = (W > 1) ? (float)j / (float)(W - 1) : 0.0f;
                float sy = fminf(u * (float)(SGRID - 1), (float)(SGRID - 1));
                float sx = fminf(v * (float)(SGRID - 1), (float)(SGRID - 1));
                int y0 = (int)sy, x0 = (int)sx;
                int y1 = min(y0 + 1, SGRID - 1);
                int x1 = min(x0 + 1, SGRID - 1);
                m_u[tid] = u;  m_v[tid] = v;
                m_wy[tid] = sy - (float)y0;
                m_wx[tid] = sx - (float)x0;
                m_geom[tid] = y0 | (y1 << 8) | (x0 << 16) | (x1 << 24);
                m_addr[tid] = (b << 11) | (i << 5) | j;
            } else {
                m_u[tid] = 0.f; m_v[tid] = 0.f;
                m_wy[tid] = 0.f; m_wx[tid] = 0.f;
                m_geom[tid] = 0;
                m_addr[tid] = -1;
            }
        }
        __syncthreads();

        // ---- phase 2: h = gelu(u*w1u + v*w1v + b1), dup {h,h} ----
        {
            int p = tid >> 2;                  // point 0..63
            int kb = (tid & 3) * 16;           // 16 k per thread
            float u = m_u[p], v = m_v[p];
            float2* dst = shh + p * HID + kb;
            #pragma unroll
            for (int c = 0; c < 16; c++) {
                int k = kb + c;
                float g = gelu_exact(u * s_w1u[k] + v * s_w1v[k] + s_b1[k]);
                dst[c] = make_float2(g, g);
            }
        }
        __syncthreads();

        // ---- GEMM: acc[pp][c] += h[p][k] * w2[k][dp] ----
        ull acc[8][4];
        #pragma unroll
        for (int pp = 0; pp < 8; pp++)
            #pragma unroll
            for (int c = 0; c < 4; c++) acc[pp][c] = 0ull;

        const ull* shh_u = (const ull*)shh;
        const ull* shw2_u = (const ull*)(smem + OFF_W2);
        const int pbase = wid * 8;

        #pragma unroll 4
        for (int k = 0; k < HID; k++) {
            ull wv[4];
            const ull* wk = shw2_u + k * 128;
            #pragma unroll
            for (int c = 0; c < 4; c++) wv[c] = wk[nx + 32 * c];
            #pragma unroll
            for (int pp = 0; pp < 8; pp++) {
                ull h2 = shh_u[(pbase + pp) * HID + k];
                #pragma unroll
                for (int c = 0; c < 4; c++)
                    asm("fma.rn.f32x2 %0, %1, %2, %3;"
                        : "=l"(acc[pp][c]) : "l"(h2), "l"(wv[c]), "l"(acc[pp][c]));
            }
        }

        // ---- epilogue: bilinear gathers + acc + b2, coalesced STG.64 ----
        {
            const float2* can2 = (const float2*)canonical + half * 128;
            float2 b2v[4];
            #pragma unroll
            for (int c = 0; c < 4; c++) b2v[c] = sb2[nx + 32 * c];

            #pragma unroll
            for (int pp = 0; pp < 8; pp++) {
                int p = pbase + pp;
                int ad = m_addr[p];
                if (ad < 0) continue;
                int geom = m_geom[p];
                int y0 = geom & 0xFF, y1 = (geom >> 8) & 0xFF;
                int x0 = (geom >> 16) & 0xFF, x1 = (geom >> 24) & 0xFF;
                float wy = m_wy[p], wx = m_wx[p];
                const float2* p00 = can2 + (size_t)(y0 * SGRID + x0) * 256;
                const float2* p01 = can2 + (size_t)(y0 * SGRID + x1) * 256;
                const float2* p10 = can2 + (size_t)(y1 * SGRID + x0) * 256;
                const float2* p11 = can2 + (size_t)(y1 * SGRID + x1) * 256;
                float w00 = (1.f - wy) * (1.f - wx), w01 = (1.f - wy) * wx;
                float w10 = wy * (1.f - wx),         w11 = wy * wx;
                float* op = out + ((size_t)ad) * DIM + half * 256;

                #pragma unroll
                for (int c = 0; c < 4; c++) {
                    int dp = nx + 32 * c;
                    float2 q00 = __ldg(p00 + dp);
                    float2 q01 = __ldg(p01 + dp);
                    float2 q10 = __ldg(p10 + dp);
                    float2 q11 = __ldg(p11 + dp);
                    float bx = w00 * q00.x + w01 * q01.x + w10 * q10.x + w11 * q11.x;
                    float by = w00 * q00.y + w01 * q01.y + w10 * q10.y + w11 * q11.y;
                    ull A = acc[pp][c];
                    float2 r;
                    r.x = __uint_as_float((unsigned)A) + bx + b2v[c].x;
                    r.y = __uint_as_float((unsigned)(A >> 32)) + by + b2v[c].y;
                    *(float2*)(op + dp * 2) = r;
                }
            }
        }

        // ---- interleaved zero/mask rows (overlap DRAM under next tile's FMA) ----
        #pragma unroll 1
        for (int z = 0; z < 4 && zr < NROWS; z++, zr += GRIDMAIN)
            do_row(zr, s_hw, out, mout, tail, tid);
    }

    // ---- remaining zero/mask rows ----
    #pragma unroll 1
    while (zr < NROWS) { do_row(zr, s_hw, out, mout, tail, tid); zr += GRIDMAIN; }

    // ---- any padding past qelems + 131072 (CTA 0) ----
    if (blockIdx.x == 0 && tail > NROWS * 32) {
        for (int e = NROWS * 32 + tid; e < tail; e += TPB)
            mout[e] = 0.0f;
    }
}

extern "C" void kernel_launch(void* const* d_in, const int* in_sizes, int n_in,
                              void* d_out, int out_size)
{
    const float* canonical = (const float*)d_in[0];
    const float* w1        = (const float*)d_in[1];
    const float* b1        = (const float*)d_in[2];
    const float* w2        = (const float*)d_in[3];
    const float* b2        = (const float*)d_in[4];
    const int*   th        = (const int*)d_in[6];
    const int*   tw        = (const int*)d_in[7];
    float* out = (float*)d_out;

    cudaFuncSetAttribute(hgq_all, cudaFuncAttributeMaxDynamicSharedMemorySize, SMEM_BYTES);
    hgq_all<<<GRIDMAIN, TPB, SMEM_BYTES>>>(canonical, w1, b1, w2, b2, th, tw,
                                           out, out_size);
}

// round 9
// speedup vs baseline: 2.8060x; 1.2197x over previous
#include <cuda_runtime.h>
#include <cstdint>

// ---------------- problem constants ----------------
#define BATCH   64
#define MAXH    64
#define MAXW    32
#define DIM     512
#define SGRID   8
#define HID     64

#define TPB       256
#define GRIDMAIN  296      // 2 CTAs per SM
#define QELEMS    (BATCH * MAXH * MAXW * DIM)
#define NROWS     (BATCH * MAXH)          // 4096 (b,i) row units

// SMEM layout (bytes)
#define OFF_W2    0        // w2 half [64 k][256 d] fp32       (65536)
#define OFF_HA    65536    // h buf0 [64 p][64 k] fp32         (16384)
#define OFF_HB    81920    // h buf1                           (16384)
#define OFF_B2    98304    // b2 half [256] fp32               (1024)
#define OFF_W1    99328    // w1u[64], w1v[64]                 (512)
#define OFF_B1    99840    // b1[64]                           (256)
#define OFF_M0    100096   // meta buf0: geom[64],addr[64],wy[64],wx[64] (1024)
#define OFF_M1    101120   // meta buf1                        (1024)
#define OFF_BASE  102144   // s_base[65]                       (260)
#define OFF_HW    102404   // s_hw[64]                         (256)
#define SMEM_BYTES 102912

typedef unsigned long long ull;

__device__ __forceinline__ float gelu_exact(float x) {
    return 0.5f * x * (1.0f + erff(x * 0.70710678118654752440f));
}

__device__ __forceinline__ ull dupf(float x) {
    ull r;
    unsigned xb = __float_as_uint(x);
    asm("mov.b64 %0, {%1, %1};" : "=l"(r) : "r"(xb));
    return r;
}

// zero/mask one (b,i) row unit
__device__ __forceinline__ void do_row(
    int r, const int* s_hw, float* __restrict__ out,
    float* __restrict__ mout, int tail, int tid)
{
    const int b = r >> 6, i = r & 63;
    const int hw = s_hw[b];
    const int H = hw >> 16, W = hw & 0xFFFF;
    float4* row = (float4*)(out + ((size_t)r) * (MAXW * DIM));
    const float4 z = make_float4(0.f, 0.f, 0.f, 0.f);
    if (i >= H) {
        #pragma unroll
        for (int e = 0; e < (MAXW * DIM / 4) / TPB; e++)   // 16 iters
            row[tid + TPB * e] = z;
    } else if (W < MAXW) {
        int start4 = W * (DIM / 4);
        int cnt4 = (MAXW - W) * (DIM / 4);
        for (int e = tid; e < cnt4; e += TPB)
            row[start4 + e] = z;
    }
    if (tail > 0 && tid < 32) {
        int idx = r * 32 + tid;
        if (idx < tail)
            mout[idx] = (i < H && tid < W) ? 1.0f : 0.0f;
    }
}

// ---------------- single fused persistent kernel ----------------
__global__ __launch_bounds__(TPB, 2) void hgq_all(
    const float* __restrict__ canonical,   // [8,8,512]
    const float* __restrict__ w1,          // [2,64]
    const float* __restrict__ b1,          // [64]
    const float* __restrict__ w2,          // [64,512]
    const float* __restrict__ b2,          // [512]
    const int*   __restrict__ th,
    const int*   __restrict__ tw,
    float*       __restrict__ out,         // [64,64,32,512] (+ mask tail)
    int          out_size)
{
    extern __shared__ char smem[];
    const float2* sb2 = (const float2*)(smem + OFF_B2);
    float* s_w1u  = (float*)(smem + OFF_W1);
    float* s_w1v  = (float*)(smem + OFF_W1 + 256);
    float* s_b1   = (float*)(smem + OFF_B1);
    int*   s_base = (int*)(smem + OFF_BASE);   // [65]
    int*   s_hw   = (int*)(smem + OFF_HW);     // [64]

    const int tid  = threadIdx.x;
    const int wid  = tid >> 5;
    const int nx   = tid & 31;
    const int half = blockIdx.x & 1;
    const int t0   = blockIdx.x >> 1;
    const int tail = out_size - QELEMS;
    float* mout = out + QELEMS;

    // ---- one-time staging ----
    {
        const float* wsrc = w2 + half * 256;
        float4* ws = (float4*)(smem + OFF_W2);
        #pragma unroll
        for (int e = 0; e < 16; e++) {
            int idx = tid + TPB * e;
            int k = idx >> 6, c4 = idx & 63;
            ws[idx] = __ldg((const float4*)(wsrc + k * DIM) + c4);
        }
        if (tid < 128)
            ((float2*)(smem + OFF_B2))[tid] = __ldg((const float2*)(b2 + half * 256) + tid);
        if (tid < 64) {
            s_w1u[tid] = __ldg(w1 + tid);
            s_w1v[tid] = __ldg(w1 + HID + tid);
            s_b1[tid]  = __ldg(b1 + tid);
            int H = min(max(__ldg(th + tid), 1), MAXH);
            int W = min(max(__ldg(tw + tid), 1), MAXW);
            s_hw[tid] = (H << 16) | W;
        }
    }
    __syncthreads();

    // ---- in-CTA prefix scan over 64 batch sizes (warp 0) ----
    if (wid == 0) {
        int hw0 = s_hw[2 * nx], hw1 = s_hw[2 * nx + 1];
        int c0 = (hw0 >> 16) * (hw0 & 0xFFFF);
        int c1 = (hw1 >> 16) * (hw1 & 0xFFFF);
        int pair = c0 + c1;
        int incl = pair;
        #pragma unroll
        for (int d = 1; d < 32; d <<= 1) {
            int n = __shfl_up_sync(0xFFFFFFFF, incl, d);
            if (nx >= d) incl += n;
        }
        int excl = incl - pair;
        s_base[2 * nx]     = excl;
        s_base[2 * nx + 1] = excl + c0;
        if (nx == 31) s_base[64] = incl;
    }
    __syncthreads();
    const int total = s_base[BATCH];

    // ---- pipelined build: h + meta for tile t into buffer sel ----
    auto build = [&](int t, int sel) {
        float* hbuf = (float*)(smem + (sel ? OFF_HB : OFF_HA));
        char* mb = smem + (sel ? OFF_M1 : OFF_M0);
        int*   m_geom = (int*)mb;
        int*   m_addr = (int*)(mb + 256);
        float* m_wy   = (float*)(mb + 512);
        float* m_wx   = (float*)(mb + 768);

        // gelu h: thread -> point tid>>2, 16 k values
        {
            int q = t * 64 + (tid >> 2);
            float u = 0.f, v = 0.f;
            if (q < total) {
                int lo = 0, hi = BATCH;
                while (hi - lo > 1) {
                    int mid = (lo + hi) >> 1;
                    if (q >= s_base[mid]) lo = mid; else hi = mid;
                }
                int hw = s_hw[lo];
                int H = hw >> 16, W = hw & 0xFFFF;
                int r = q - s_base[lo];
                int i = r / W;
                int j = r - i * W;
                u = (H > 1) ? (float)i / (float)(H - 1) : 0.0f;
                v = (W > 1) ? (float)j / (float)(W - 1) : 0.0f;
            }
            int kb = (tid & 3) * 16;
            float* dst = hbuf + (tid >> 2) * HID + kb;
            #pragma unroll
            for (int c = 0; c < 16; c++) {
                int k = kb + c;
                dst[c] = gelu_exact(u * s_w1u[k] + v * s_w1v[k] + s_b1[k]);
            }
        }
        // meta: threads 0..63
        if (tid < 64) {
            int q = t * 64 + tid;
            if (q < total) {
                int lo = 0, hi = BATCH;
                while (hi - lo > 1) {
                    int mid = (lo + hi) >> 1;
                    if (q >= s_base[mid]) lo = mid; else hi = mid;
                }
                int b = lo;
                int hw = s_hw[b];
                int H = hw >> 16, W = hw & 0xFFFF;
                int r = q - s_base[b];
                int i = r / W;
                int j = r - i * W;
                float u = (H > 1) ? (float)i / (float)(H - 1) : 0.0f;
                float v = (W > 1) ? (float)j / (float)(W - 1) : 0.0f;
                float sy = fminf(u * (float)(SGRID - 1), (float)(SGRID - 1));
                float sx = fminf(v * (float)(SGRID - 1), (float)(SGRID - 1));
                int y0 = (int)sy, x0 = (int)sx;
                int y1 = min(y0 + 1, SGRID - 1);
                int x1 = min(x0 + 1, SGRID - 1);
                m_wy[tid] = sy - (float)y0;
                m_wx[tid] = sx - (float)x0;
                m_geom[tid] = y0 | (y1 << 8) | (x0 << 16) | (x1 << 24);
                m_addr[tid] = (b << 11) | (i << 5) | j;
            } else {
                m_wy[tid] = 0.f; m_wx[tid] = 0.f;
                m_geom[tid] = 0;
                m_addr[tid] = -1;
            }
        }
    };

    int zr = blockIdx.x;       // zero/mask row cursor

    // prologue: build first tile
    if (t0 * 64 < total) build(t0, 0);
    __syncthreads();

    int sel = 0;
    for (int t = t0; t * 64 < total; t += 148) {
        const float* hbuf = (const float*)(smem + (sel ? OFF_HB : OFF_HA));
        const char* mb = smem + (sel ? OFF_M1 : OFF_M0);
        const int*   m_geom = (const int*)mb;
        const int*   m_addr = (const int*)(mb + 256);
        const float* m_wy   = (const float*)(mb + 512);
        const float* m_wx   = (const float*)(mb + 768);

        // ---- GEMM: acc[pp][c] += h[p][k] * w2[k][dp] ----
        ull acc[8][4];
        #pragma unroll
        for (int pp = 0; pp < 8; pp++)
            #pragma unroll
            for (int c = 0; c < 4; c++) acc[pp][c] = 0ull;

        const ull* shw2_u = (const ull*)(smem + OFF_W2);
        const int pbase = wid * 8;

        #pragma unroll 2
        for (int k = 0; k < HID; k += 2) {
            ull wv0[4], wv1[4];
            const ull* wk0 = shw2_u + k * 128;
            #pragma unroll
            for (int c = 0; c < 4; c++) {
                wv0[c] = wk0[nx + 32 * c];
                wv1[c] = wk0[128 + nx + 32 * c];
            }
            #pragma unroll
            for (int pp = 0; pp < 8; pp++) {
                float2 hv = *(const float2*)(hbuf + (pbase + pp) * HID + k);
                ull h0 = dupf(hv.x), h1 = dupf(hv.y);
                #pragma unroll
                for (int c = 0; c < 4; c++) {
                    asm("fma.rn.f32x2 %0, %1, %2, %3;"
                        : "=l"(acc[pp][c]) : "l"(h0), "l"(wv0[c]), "l"(acc[pp][c]));
                    asm("fma.rn.f32x2 %0, %1, %2, %3;"
                        : "=l"(acc[pp][c]) : "l"(h1), "l"(wv1[c]), "l"(acc[pp][c]));
                }
            }
        }

        // ---- epilogue: bilinear gathers + acc + b2, coalesced STG.64 ----
        {
            const float2* can2 = (const float2*)canonical + half * 128;
            float2 b2v[4];
            #pragma unroll
            for (int c = 0; c < 4; c++) b2v[c] = sb2[nx + 32 * c];

            #pragma unroll
            for (int pp = 0; pp < 8; pp++) {
                int p = pbase + pp;
                int ad = m_addr[p];
                if (ad < 0) continue;
                int geom = m_geom[p];
                int y0 = geom & 0xFF, y1 = (geom >> 8) & 0xFF;
                int x0 = (geom >> 16) & 0xFF, x1 = (geom >> 24) & 0xFF;
                float wy = m_wy[p], wx = m_wx[p];
                const float2* p00 = can2 + (size_t)(y0 * SGRID + x0) * 256;
                const float2* p01 = can2 + (size_t)(y0 * SGRID + x1) * 256;
                const float2* p10 = can2 + (size_t)(y1 * SGRID + x0) * 256;
                const float2* p11 = can2 + (size_t)(y1 * SGRID + x1) * 256;
                float w00 = (1.f - wy) * (1.f - wx), w01 = (1.f - wy) * wx;
                float w10 = wy * (1.f - wx),         w11 = wy * wx;
                float* op = out + ((size_t)ad) * DIM + half * 256;

                #pragma unroll
                for (int c = 0; c < 4; c++) {
                    int dp = nx + 32 * c;
                    float2 q00 = __ldg(p00 + dp);
                    float2 q01 = __ldg(p01 + dp);
                    float2 q10 = __ldg(p10 + dp);
                    float2 q11 = __ldg(p11 + dp);
                    float bx = w00 * q00.x + w01 * q01.x + w10 * q10.x + w11 * q11.x;
                    float by = w00 * q00.y + w01 * q01.y + w10 * q10.y + w11 * q11.y;
                    ull A = acc[pp][c];
                    float2 r;
                    r.x = __uint_as_float((unsigned)A) + bx + b2v[c].x;
                    r.y = __uint_as_float((unsigned)(A >> 32)) + by + b2v[c].y;
                    *(float2*)(op + dp * 2) = r;
                }
            }
        }

        // ---- build next tile into other buffer (overlaps with other warps' GEMM) ----
        if ((t + 148) * 64 < total) build(t + 148, sel ^ 1);

        // ---- interleaved zero/mask rows ----
        #pragma unroll 1
        for (int z = 0; z < 4 && zr < NROWS; z++, zr += GRIDMAIN)
            do_row(zr, s_hw, out, mout, tail, tid);

        __syncthreads();        // one barrier per tile
        sel ^= 1;
    }

    // ---- remaining zero/mask rows ----
    #pragma unroll 1
    while (zr < NROWS) { do_row(zr, s_hw, out, mout, tail, tid); zr += GRIDMAIN; }

    // ---- any padding past qelems + 131072 (CTA 0) ----
    if (blockIdx.x == 0 && tail > NROWS * 32) {
        for (int e = NROWS * 32 + tid; e < tail; e += TPB)
            mout[e] = 0.0f;
    }
}

extern "C" void kernel_launch(void* const* d_in, const int* in_sizes, int n_in,
                              void* d_out, int out_size)
{
    const float* canonical = (const float*)d_in[0];
    const float* w1        = (const float*)d_in[1];
    const float* b1        = (const float*)d_in[2];
    const float* w2        = (const float*)d_in[3];
    const float* b2        = (const float*)d_in[4];
    const int*   th        = (const int*)d_in[6];
    const int*   tw        = (const int*)d_in[7];
    float* out = (float*)d_out;

    cudaFuncSetAttribute(hgq_all, cudaFuncAttributeMaxDynamicSharedMemorySize, SMEM_BYTES);
    hgq_all<<<GRIDMAIN, TPB, SMEM_BYTES>>>(canonical, w1, b1, w2, b2, th, tw,
                                           out, out_size);
}